// round 12
// baseline (speedup 1.0000x reference)
#include <cuda_runtime.h>
#include <cuda_fp16.h>
#include <cstdint>
#include <cstdio>

// ---------------------------------------------------------------------------
// EdgeTAM RoPE cross-attention, sm_100a (compute_100 target: no tcgen05).
// R12: R10 base (best: 356.3us) + fp16 RoPE tables loaded as half2 pairs
//      in the projection epilogues (halves the scattered gather traffic).
// ---------------------------------------------------------------------------

#define DEVFN __device__ __forceinline__

constexpr int BB   = 8;
constexpr int SQ   = 4096;
constexpr int SK   = 2304;
constexpr int DH   = 256;
constexpr int MQ   = BB * SQ;   // 32768
constexpr int MK   = BB * SK;   // 18432
constexpr float QSCALE = 0.0625f * 1.4426950408889634f;  // 1/16 * log2(e)

// fp16 scratch
__device__ __align__(16) __half g_Q[(size_t)MQ * DH];
__device__ __align__(16) __half g_K[(size_t)MK * DH];
__device__ __align__(16) __half g_V[(size_t)MK * DH];
__device__ __align__(16) __half g_O[(size_t)MQ * DH];
// fp16 copies of inputs / weights / rope tables (pre-converted)
__device__ __align__(16) __half g_Aq[(size_t)MQ * DH];
__device__ __align__(16) __half g_Ak[(size_t)MK * 64];
__device__ __align__(16) __half g_Av[(size_t)MK * 64];
__device__ __align__(16) __half g_Wq[256 * 256];
__device__ __align__(16) __half g_Wk[256 * 64];
__device__ __align__(16) __half g_Wv[256 * 64];
__device__ __align__(16) __half g_Wo[256 * 256];
__device__ __align__(16) __half g_Cq[(size_t)SQ * DH];   // cos (q), 4096x256
__device__ __align__(16) __half g_Sq[(size_t)SQ * DH];   // sin (q)
__device__ __align__(16) __half g_Ck[256 * DH];          // cos_k, 256x256
__device__ __align__(16) __half g_Sk[256 * DH];          // sin_k

DEVFN uint32_t cvta_s(const void* p) { return (uint32_t)__cvta_generic_to_shared(p); }

DEVFN void ldsm_x4(uint32_t* r, uint32_t addr) {
    asm volatile("ldmatrix.sync.aligned.m8n8.x4.shared.b16 {%0,%1,%2,%3},[%4];"
                 : "=r"(r[0]), "=r"(r[1]), "=r"(r[2]), "=r"(r[3]) : "r"(addr));
}
DEVFN void ldsm_x4_t(uint32_t* r, uint32_t addr) {
    asm volatile("ldmatrix.sync.aligned.m8n8.x4.trans.shared.b16 {%0,%1,%2,%3},[%4];"
                 : "=r"(r[0]), "=r"(r[1]), "=r"(r[2]), "=r"(r[3]) : "r"(addr));
}
DEVFN void mma16816(float* c, const uint32_t* a, uint32_t b0, uint32_t b1) {
    asm volatile("mma.sync.aligned.m16n8k16.row.col.f32.f16.f16.f32 "
                 "{%0,%1,%2,%3},{%4,%5,%6,%7},{%8,%9},{%0,%1,%2,%3};"
                 : "+f"(c[0]), "+f"(c[1]), "+f"(c[2]), "+f"(c[3])
                 : "r"(a[0]), "r"(a[1]), "r"(a[2]), "r"(a[3]), "r"(b0), "r"(b1));
}
DEVFN void cpa16(uint32_t dst, const void* src) {
    asm volatile("cp.async.cg.shared.global [%0],[%1],16;" :: "r"(dst), "l"(src));
}
DEVFN void cpa_commit() { asm volatile("cp.async.commit_group;"); }
DEVFN void cpa_wait0()  { asm volatile("cp.async.wait_group 0;"); }

// ---------------------------------------------------------------------------
// Pre-convert: fp32 -> fp16 for inputs, weights, and rope tables.
// ---------------------------------------------------------------------------
DEVFN void cvt8(const float* __restrict__ s, __half* __restrict__ d) {
    const float4 f0 = *(const float4*)s;
    const float4 f1 = *(const float4*)(s + 4);
    __half2 h[4] = { __floats2half2_rn(f0.x, f0.y), __floats2half2_rn(f0.z, f0.w),
                     __floats2half2_rn(f1.x, f1.y), __floats2half2_rn(f1.z, f1.w) };
    *(uint4*)d = *(uint4*)h;
}

constexpr size_t NQE  = (size_t)MQ * DH;     // 8388608
constexpr size_t NKE  = (size_t)MK * 64;     // 1179648
constexpr size_t NWQO = 256 * 256;
constexpr size_t NWKV = 256 * 64;
constexpr size_t NQC  = (size_t)SQ * DH;     // 1048576
constexpr size_t NKC  = 256 * DH;            // 65536
constexpr size_t NCVT = NQE + 2 * NKE + 2 * NWQO + 2 * NWKV + 2 * NQC + 2 * NKC; // 13139968
constexpr int    CVT_BLOCKS = (int)(NCVT / 8 / 256);   // 6416

__global__ __launch_bounds__(256, 8)
void cvt_kernel(const float* __restrict__ q, const float* __restrict__ k,
                const float* __restrict__ v,
                const float* __restrict__ wq, const float* __restrict__ wk,
                const float* __restrict__ wv, const float* __restrict__ wo,
                const float* __restrict__ cq, const float* __restrict__ sq,
                const float* __restrict__ ck, const float* __restrict__ sk)
{
    size_t i = ((size_t)blockIdx.x * 256 + threadIdx.x) * 8;
    if (i < NQE)  { cvt8(q  + i, g_Aq + i); return; }  i -= NQE;
    if (i < NKE)  { cvt8(k  + i, g_Ak + i); return; }  i -= NKE;
    if (i < NKE)  { cvt8(v  + i, g_Av + i); return; }  i -= NKE;
    if (i < NWQO) { cvt8(wq + i, g_Wq + i); return; }  i -= NWQO;
    if (i < NWKV) { cvt8(wk + i, g_Wk + i); return; }  i -= NWKV;
    if (i < NWKV) { cvt8(wv + i, g_Wv + i); return; }  i -= NWKV;
    if (i < NWQO) { cvt8(wo + i, g_Wo + i); return; }  i -= NWQO;
    if (i < NQC)  { cvt8(cq + i, g_Cq + i); return; }  i -= NQC;
    if (i < NQC)  { cvt8(sq + i, g_Sq + i); return; }  i -= NQC;
    if (i < NKC)  { cvt8(ck + i, g_Ck + i); return; }  i -= NKC;
    cvt8(sk + i, g_Sk + i);
}

// ---------------------------------------------------------------------------
// Projection GEMM body (R10 form): 128x256 tile, cp.async fp16 fills.
// EPI: 0=q(rope+scale->g_Q) 1=k(rope_k->g_K) 2=v(->g_V) 3=o(->fp32 out)
// RoPE tables read as __half2 pairs (n even by construction).
// ---------------------------------------------------------------------------
template <int KIN, int EPI>
__device__ void proj_body(int m0, const __half* __restrict__ Ah,
                          const __half* __restrict__ Wh,
                          const float* __restrict__ bias,
                          float* __restrict__ outF, __half* smbase)
{
    constexpr int KP  = KIN + 8;
    constexpr int KC  = KIN / 8;
    constexpr int KCS = (KIN == 256) ? 5 : 3;
    __half* Ws = smbase;
    __half* As = smbase + 256 * KP;
    const int tid = threadIdx.x;
    const uint32_t WsB = cvta_s(Ws), AsB = cvta_s(As);

    for (int c = tid; c < 256 * KC; c += 256) {
        int n = c >> KCS, k = (c & (KC - 1)) * 8;
        cpa16(WsB + (uint32_t)((n * KP + k) * 2), Wh + (size_t)n * KIN + k);
    }
    for (int c = tid; c < 128 * KC; c += 256) {
        int r = c >> KCS, k = (c & (KC - 1)) * 8;
        cpa16(AsB + (uint32_t)((r * KP + k) * 2), Ah + (size_t)(m0 + r) * KIN + k);
    }
    cpa_commit(); cpa_wait0();
    __syncthreads();

    const int warp = tid >> 5, lane = tid & 31;
    const int mb   = warp * 16;

    float acc[32][4];
#pragma unroll
    for (int i = 0; i < 32; i++) { acc[i][0] = acc[i][1] = acc[i][2] = acc[i][3] = 0.f; }

    const uint32_t aBase =
        AsB + (uint32_t)((((mb + (lane & 15)) * KP) + (lane >> 4) * 8) * 2);
    const int bmi = lane >> 3, bri = lane & 7;

#pragma unroll
    for (int kk = 0; kk < KIN; kk += 16) {
        uint32_t a[4];
        ldsm_x4(a, aBase + kk * 2);
#pragma unroll
        for (int nf = 0; nf < 32; nf += 2) {
            uint32_t b[4];
            int rowB = nf * 8 + (bmi >> 1) * 8 + bri;
            int colB = kk + (bmi & 1) * 8;
            ldsm_x4(b, WsB + (uint32_t)((rowB * KP + colB) * 2));
            mma16816(acc[nf],     a, b[0], b[1]);
            mma16816(acc[nf + 1], a, b[2], b[3]);
        }
    }

    const int r0 = m0 + mb + (lane >> 2);
    const int nb = (lane & 3) * 2;
#pragma unroll
    for (int h = 0; h < 2; h++) {
        const int r = r0 + h * 8;
        const __half* csr = nullptr;
        const __half* snr = nullptr;
        if constexpr (EPI == 0) {
            int s = r & (SQ - 1);
            csr = g_Cq + (size_t)s * DH; snr = g_Sq + (size_t)s * DH;
        }
        if constexpr (EPI == 1) {
            int t = r % SK;
            if (t < 2240) {
                int p = t % 320;
                if (p >= 64) { csr = g_Ck + (size_t)(p - 64) * DH; snr = g_Sk + (size_t)(p - 64) * DH; }
            }
        }
#pragma unroll
        for (int nf = 0; nf < 32; nf++) {
            const int n = nf * 8 + nb;
            float x0 = acc[nf][h * 2 + 0] + bias[n];
            float x1 = acc[nf][h * 2 + 1] + bias[n + 1];
            if constexpr (EPI == 0) {
                float2 cv = __half22float2(*(const __half2*)&csr[n]);
                float2 sv = __half22float2(*(const __half2*)&snr[n]);
                float y0 = (x0 * cv.x - x1 * sv.x) * QSCALE;
                float y1 = (x1 * cv.y + x0 * sv.y) * QSCALE;
                *(__half2*)&g_Q[(size_t)r * DH + n] = __floats2half2_rn(y0, y1);
            } else if constexpr (EPI == 1) {
                float y0 = x0, y1 = x1;
                if (csr) {
                    float2 cv = __half22float2(*(const __half2*)&csr[n]);
                    float2 sv = __half22float2(*(const __half2*)&snr[n]);
                    y0 = x0 * cv.x - x1 * sv.x;
                    y1 = x1 * cv.y + x0 * sv.y;
                }
                *(__half2*)&g_K[(size_t)r * DH + n] = __floats2half2_rn(y0, y1);
            } else if constexpr (EPI == 2) {
                *(__half2*)&g_V[(size_t)r * DH + n] = __floats2half2_rn(x0, x1);
            } else {
                *(float2*)&outF[(size_t)r * DH + n] = make_float2(x0, x1);
            }
        }
    }
}

// merged q/k/v projection: blocks [0,256)=Q, [256,400)=K, [400,544)=V
__global__ __launch_bounds__(256, 1)
void qkv_kernel(const float* __restrict__ q_b, const float* __restrict__ k_b,
                const float* __restrict__ v_b)
{
    extern __shared__ __half sm[];
    const int bx = blockIdx.x;
    if (bx < 256)      proj_body<256, 0>(bx * 128, g_Aq, g_Wq, q_b, nullptr, sm);
    else if (bx < 400) proj_body<64, 1>((bx - 256) * 128, g_Ak, g_Wk, k_b, nullptr, sm);
    else               proj_body<64, 2>((bx - 400) * 128, g_Av, g_Wv, v_b, nullptr, sm);
}

__global__ __launch_bounds__(256, 1)
void o_kernel(const float* __restrict__ o_b, float* __restrict__ out)
{
    extern __shared__ __half sm[];
    proj_body<256, 3>(blockIdx.x * 128, g_O, g_Wo, o_b, out, sm);
}

// ---------------------------------------------------------------------------
// Flash attention (R8/R10 form): cross-chunk software pipeline.
// ---------------------------------------------------------------------------
constexpr int BM = 128, BN = 64, DP = 264;
constexpr int NCH = SK / BN;                 // 36
constexpr int SMEM_FLASH = (BM * DP + 4 * BN * DP) * 2;   // 202752

__global__ __launch_bounds__(256, 1)
void flash_kernel()
{
    extern __shared__ __half sm[];
    const int tid = threadIdx.x;
    const int b   = blockIdx.y;
    const int m0  = blockIdx.x * BM;

    const __half* Qgp = g_Q + ((size_t)b * SQ + m0) * DH;
    const __half* Kgp = g_K + (size_t)b * SK * DH;
    const __half* Vgp = g_V + (size_t)b * SK * DH;

    const uint32_t QsB = cvta_s(sm);
    const uint32_t KsB = QsB + BM * DP * 2;
    const uint32_t VsB = KsB + 2 * BN * DP * 2;

    for (int i = tid; i < BM * 32; i += 256) {
        int r = i >> 5, c = i & 31;
        cpa16(QsB + (uint32_t)((r * DP + c * 8) * 2), Qgp + (size_t)r * DH + c * 8);
    }
    for (int i = tid; i < BN * 32; i += 256) {
        int r = i >> 5, c = i & 31;
        cpa16(KsB + (uint32_t)((r * DP + c * 8) * 2), Kgp + (size_t)r * DH + c * 8);
    }
    cpa_commit();
    for (int i = tid; i < BN * 32; i += 256) {
        int r = i >> 5, c = i & 31;
        cpa16(KsB + (uint32_t)(BN * DP * 2 + (r * DP + c * 8) * 2),
              Kgp + (size_t)(BN + r) * DH + c * 8);
        cpa16(VsB + (uint32_t)((r * DP + c * 8) * 2), Vgp + (size_t)r * DH + c * 8);
    }
    cpa_commit();
    cpa_wait0();
    __syncthreads();

    const int warp = tid >> 5, lane = tid & 31;
    const int mb   = warp * 16;

    float oacc[32][4];
#pragma unroll
    for (int i = 0; i < 32; i++) { oacc[i][0] = oacc[i][1] = oacc[i][2] = oacc[i][3] = 0.f; }
    float l0 = 0.f, l1 = 0.f;
    float sacc[8][4];
    uint32_t pfr[8][2];

    const uint32_t aQBase =
        QsB + (uint32_t)((((mb + (lane & 15)) * DP) + (lane >> 4) * 8) * 2);
    const int bmi = lane >> 3, bri = lane & 7;

    auto do_qk = [&](uint32_t Kc) {
#pragma unroll
        for (int i = 0; i < 8; i++) { sacc[i][0] = sacc[i][1] = sacc[i][2] = sacc[i][3] = 0.f; }
#pragma unroll
        for (int kk = 0; kk < DH; kk += 16) {
            uint32_t a[4];
            ldsm_x4(a, aQBase + kk * 2);
#pragma unroll
            for (int jn = 0; jn < 8; jn += 2) {
                uint32_t bf[4];
                int rowB = jn * 8 + (bmi >> 1) * 8 + bri;
                int colB = kk + (bmi & 1) * 8;
                ldsm_x4(bf, Kc + (uint32_t)((rowB * DP + colB) * 2));
                mma16816(sacc[jn],     a, bf[0], bf[1]);
                mma16816(sacc[jn + 1], a, bf[2], bf[3]);
            }
        }
    };
    auto do_pv = [&](uint32_t Vc) {
#pragma unroll
        for (int ks = 0; ks < 4; ks++) {
            uint32_t a2[4] = { pfr[2 * ks][0], pfr[2 * ks][1],
                               pfr[2 * ks + 1][0], pfr[2 * ks + 1][1] };
#pragma unroll
            for (int nf = 0; nf < 32; nf += 2) {
                uint32_t bf[4];
                int rowV = ks * 16 + (bmi & 1) * 8 + bri;
                int colV = nf * 8 + (bmi >> 1) * 8;
                ldsm_x4_t(bf, Vc + (uint32_t)((rowV * DP + colV) * 2));
                mma16816(oacc[nf],     a2, bf[0], bf[1]);
                mma16816(oacc[nf + 1], a2, bf[2], bf[3]);
            }
        }
    };

    do_qk(KsB);
    __syncthreads();

    const __half2 clamp15 = __float2half2_rn(15.f);

#pragma unroll 1
    for (int i = 1; i <= NCH; i++) {
        if (i < NCH) {
            if (i + 1 < NCH) {
                const __half* Kn = Kgp + (size_t)(i + 1) * BN * DH;
                const uint32_t Kd = KsB + (uint32_t)(((i + 1) & 1) * BN * DP * 2);
                for (int t = tid; t < BN * 32; t += 256) {
                    int r = t >> 5, c = t & 31;
                    cpa16(Kd + (uint32_t)((r * DP + c * 8) * 2), Kn + (size_t)r * DH + c * 8);
                }
            }
            {
                const __half* Vn = Vgp + (size_t)i * BN * DH;
                const uint32_t Vd = VsB + (uint32_t)((i & 1) * BN * DP * 2);
                for (int t = tid; t < BN * 32; t += 256) {
                    int r = t >> 5, c = t & 31;
                    cpa16(Vd + (uint32_t)((r * DP + c * 8) * 2), Vn + (size_t)r * DH + c * 8);
                }
            }
            cpa_commit();
        }

        __half2 t0 = __float2half2_rn(0.f), t1 = __float2half2_rn(0.f);
#pragma unroll
        for (int j = 0; j < 8; j++) {
            __half2 h0 = __floats2half2_rn(sacc[j][0], sacc[j][1]);
            __half2 h1 = __floats2half2_rn(sacc[j][2], sacc[j][3]);
            h0 = h2exp2(__hmin2(h0, clamp15));
            h1 = h2exp2(__hmin2(h1, clamp15));
            pfr[j][0] = *(uint32_t*)&h0;
            pfr[j][1] = *(uint32_t*)&h1;
            t0 = __hadd2(t0, h0);
            t1 = __hadd2(t1, h1);
        }
        {
            float2 f0 = __half22float2(t0), f1 = __half22float2(t1);
            l0 += f0.x + f0.y;
            l1 += f1.x + f1.y;
        }

        if (i < NCH) do_qk(KsB + (uint32_t)((i & 1) * BN * DP * 2));
        do_pv(VsB + (uint32_t)(((i - 1) & 1) * BN * DP * 2));

        if (i < NCH) { cpa_wait0(); __syncthreads(); }
    }

    l0 += __shfl_xor_sync(0xffffffffu, l0, 1);
    l0 += __shfl_xor_sync(0xffffffffu, l0, 2);
    l1 += __shfl_xor_sync(0xffffffffu, l1, 1);
    l1 += __shfl_xor_sync(0xffffffffu, l1, 2);
    const float inv0 = 1.f / l0, inv1 = 1.f / l1;
    const size_t rowbase = (size_t)b * SQ + m0 + mb + (lane >> 2);
#pragma unroll
    for (int nf = 0; nf < 32; nf++) {
        const int n = nf * 8 + (lane & 3) * 2;
        *(__half2*)&g_O[rowbase * DH + n] =
            __floats2half2_rn(oacc[nf][0] * inv0, oacc[nf][1] * inv0);
        *(__half2*)&g_O[(rowbase + 8) * DH + n] =
            __floats2half2_rn(oacc[nf][2] * inv1, oacc[nf][3] * inv1);
    }
}

// ---------------------------------------------------------------------------
extern "C" void kernel_launch(void* const* d_in, const int* in_sizes, int n_in,
                              void* d_out, int out_size)
{
    (void)in_sizes; (void)n_in; (void)out_size;
    const float* query = (const float*)d_in[0];
    const float* key   = (const float*)d_in[1];
    const float* value = (const float*)d_in[2];
    const float* q_w   = (const float*)d_in[3];
    const float* q_b   = (const float*)d_in[4];
    const float* k_w   = (const float*)d_in[5];
    const float* k_b   = (const float*)d_in[6];
    const float* v_w   = (const float*)d_in[7];
    const float* v_b   = (const float*)d_in[8];
    const float* o_w   = (const float*)d_in[9];
    const float* o_b   = (const float*)d_in[10];
    const float* cosq  = (const float*)d_in[11];
    const float* sinq  = (const float*)d_in[12];
    const float* cosk  = (const float*)d_in[13];
    const float* sink  = (const float*)d_in[14];
    float* out = (float*)d_out;

    constexpr int SMEM_BIG = (256 + 128) * 264 * 2;  // 202752

    cudaFuncSetAttribute(qkv_kernel,   cudaFuncAttributeMaxDynamicSharedMemorySize, SMEM_BIG);
    cudaFuncSetAttribute(o_kernel,     cudaFuncAttributeMaxDynamicSharedMemorySize, SMEM_BIG);
    cudaFuncSetAttribute(flash_kernel, cudaFuncAttributeMaxDynamicSharedMemorySize, SMEM_FLASH);

    cvt_kernel<<<CVT_BLOCKS, 256>>>(query, key, value, q_w, k_w, v_w, o_w,
                                    cosq, sinq, cosk, sink);
    qkv_kernel<<<544, 256, SMEM_BIG>>>(q_b, k_b, v_b);
    flash_kernel<<<dim3(SQ / BM, BB), 256, SMEM_FLASH>>>();
    o_kernel<<<MQ / 128, 256, SMEM_BIG>>>(o_b, out);
}

// round 13
// speedup vs baseline: 1.0600x; 1.0600x over previous
#include <cuda_runtime.h>
#include <cuda_fp16.h>
#include <cstdint>
#include <cstdio>

// ---------------------------------------------------------------------------
// EdgeTAM RoPE cross-attention, sm_100a (compute_100 target: no tcgen05).
// R13: R10 base + o-projection FUSED into flash's epilogue:
//   - normalized O repacked from C-fragments to A-fragments in registers
//   - Wo prefetched into the dead K/V smem regions during the last chunk
//   - per-warp 16x256x256 GEMM writes fp32 out + bias directly
//   Removes o_kernel launch + 32MB g_O round trip.
// ---------------------------------------------------------------------------

#define DEVFN __device__ __forceinline__

constexpr int BB   = 8;
constexpr int SQ   = 4096;
constexpr int SK   = 2304;
constexpr int DH   = 256;
constexpr int MQ   = BB * SQ;   // 32768
constexpr int MK   = BB * SK;   // 18432
constexpr float QSCALE = 0.0625f * 1.4426950408889634f;  // 1/16 * log2(e)

// fp16 scratch
__device__ __align__(16) __half g_Q[(size_t)MQ * DH];
__device__ __align__(16) __half g_K[(size_t)MK * DH];
__device__ __align__(16) __half g_V[(size_t)MK * DH];
// fp16 copies of inputs / weights (pre-converted)
__device__ __align__(16) __half g_Aq[(size_t)MQ * DH];
__device__ __align__(16) __half g_Ak[(size_t)MK * 64];
__device__ __align__(16) __half g_Av[(size_t)MK * 64];
__device__ __align__(16) __half g_Wq[256 * 256];
__device__ __align__(16) __half g_Wk[256 * 64];
__device__ __align__(16) __half g_Wv[256 * 64];
__device__ __align__(16) __half g_Wo[256 * 256];

DEVFN uint32_t cvta_s(const void* p) { return (uint32_t)__cvta_generic_to_shared(p); }

DEVFN void ldsm_x4(uint32_t* r, uint32_t addr) {
    asm volatile("ldmatrix.sync.aligned.m8n8.x4.shared.b16 {%0,%1,%2,%3},[%4];"
                 : "=r"(r[0]), "=r"(r[1]), "=r"(r[2]), "=r"(r[3]) : "r"(addr));
}
DEVFN void ldsm_x4_t(uint32_t* r, uint32_t addr) {
    asm volatile("ldmatrix.sync.aligned.m8n8.x4.trans.shared.b16 {%0,%1,%2,%3},[%4];"
                 : "=r"(r[0]), "=r"(r[1]), "=r"(r[2]), "=r"(r[3]) : "r"(addr));
}
DEVFN void mma16816(float* c, const uint32_t* a, uint32_t b0, uint32_t b1) {
    asm volatile("mma.sync.aligned.m16n8k16.row.col.f32.f16.f16.f32 "
                 "{%0,%1,%2,%3},{%4,%5,%6,%7},{%8,%9},{%0,%1,%2,%3};"
                 : "+f"(c[0]), "+f"(c[1]), "+f"(c[2]), "+f"(c[3])
                 : "r"(a[0]), "r"(a[1]), "r"(a[2]), "r"(a[3]), "r"(b0), "r"(b1));
}
DEVFN void cpa16(uint32_t dst, const void* src) {
    asm volatile("cp.async.cg.shared.global [%0],[%1],16;" :: "r"(dst), "l"(src));
}
DEVFN void cpa_commit() { asm volatile("cp.async.commit_group;"); }
DEVFN void cpa_wait0()  { asm volatile("cp.async.wait_group 0;"); }

// ---------------------------------------------------------------------------
// Pre-convert: fp32 -> fp16 for inputs and weights (bandwidth-bound).
// ---------------------------------------------------------------------------
DEVFN void cvt8(const float* __restrict__ s, __half* __restrict__ d) {
    const float4 f0 = *(const float4*)s;
    const float4 f1 = *(const float4*)(s + 4);
    __half2 h[4] = { __floats2half2_rn(f0.x, f0.y), __floats2half2_rn(f0.z, f0.w),
                     __floats2half2_rn(f1.x, f1.y), __floats2half2_rn(f1.z, f1.w) };
    *(uint4*)d = *(uint4*)h;
}

constexpr size_t NQE  = (size_t)MQ * DH;
constexpr size_t NKE  = (size_t)MK * 64;
constexpr size_t NWQO = 256 * 256;
constexpr size_t NWKV = 256 * 64;
constexpr size_t NCVT = NQE + 2 * NKE + 2 * NWQO + 2 * NWKV;
constexpr int    CVT_BLOCKS = (int)(NCVT / 8 / 256);

__global__ __launch_bounds__(256, 8)
void cvt_kernel(const float* __restrict__ q, const float* __restrict__ k,
                const float* __restrict__ v,
                const float* __restrict__ wq, const float* __restrict__ wk,
                const float* __restrict__ wv, const float* __restrict__ wo)
{
    size_t i = ((size_t)blockIdx.x * 256 + threadIdx.x) * 8;
    if (i < NQE)  { cvt8(q  + i, g_Aq + i); return; }  i -= NQE;
    if (i < NKE)  { cvt8(k  + i, g_Ak + i); return; }  i -= NKE;
    if (i < NKE)  { cvt8(v  + i, g_Av + i); return; }  i -= NKE;
    if (i < NWQO) { cvt8(wq + i, g_Wq + i); return; }  i -= NWQO;
    if (i < NWKV) { cvt8(wk + i, g_Wk + i); return; }  i -= NWKV;
    if (i < NWKV) { cvt8(wv + i, g_Wv + i); return; }  i -= NWKV;
    cvt8(wo + i, g_Wo + i);
}

// ---------------------------------------------------------------------------
// Projection GEMM body (R10 form): 128x256 tile, cp.async fp16 fills.
// EPI: 0=q(rope+scale->g_Q) 1=k(rope_k->g_K) 2=v(->g_V)
// ---------------------------------------------------------------------------
template <int KIN, int EPI>
__device__ void proj_body(int m0, const __half* __restrict__ Ah,
                          const __half* __restrict__ Wh,
                          const float* __restrict__ bias,
                          const float* __restrict__ cs, const float* __restrict__ sn,
                          __half* smbase)
{
    constexpr int KP  = KIN + 8;
    constexpr int KC  = KIN / 8;
    constexpr int KCS = (KIN == 256) ? 5 : 3;
    __half* Ws = smbase;
    __half* As = smbase + 256 * KP;
    const int tid = threadIdx.x;
    const uint32_t WsB = cvta_s(Ws), AsB = cvta_s(As);

    for (int c = tid; c < 256 * KC; c += 256) {
        int n = c >> KCS, k = (c & (KC - 1)) * 8;
        cpa16(WsB + (uint32_t)((n * KP + k) * 2), Wh + (size_t)n * KIN + k);
    }
    for (int c = tid; c < 128 * KC; c += 256) {
        int r = c >> KCS, k = (c & (KC - 1)) * 8;
        cpa16(AsB + (uint32_t)((r * KP + k) * 2), Ah + (size_t)(m0 + r) * KIN + k);
    }
    cpa_commit(); cpa_wait0();
    __syncthreads();

    const int warp = tid >> 5, lane = tid & 31;
    const int mb   = warp * 16;

    float acc[32][4];
#pragma unroll
    for (int i = 0; i < 32; i++) { acc[i][0] = acc[i][1] = acc[i][2] = acc[i][3] = 0.f; }

    const uint32_t aBase =
        AsB + (uint32_t)((((mb + (lane & 15)) * KP) + (lane >> 4) * 8) * 2);
    const int bmi = lane >> 3, bri = lane & 7;

#pragma unroll
    for (int kk = 0; kk < KIN; kk += 16) {
        uint32_t a[4];
        ldsm_x4(a, aBase + kk * 2);
#pragma unroll
        for (int nf = 0; nf < 32; nf += 2) {
            uint32_t b[4];
            int rowB = nf * 8 + (bmi >> 1) * 8 + bri;
            int colB = kk + (bmi & 1) * 8;
            ldsm_x4(b, WsB + (uint32_t)((rowB * KP + colB) * 2));
            mma16816(acc[nf],     a, b[0], b[1]);
            mma16816(acc[nf + 1], a, b[2], b[3]);
        }
    }

    const int r0 = m0 + mb + (lane >> 2);
    const int nb = (lane & 3) * 2;
#pragma unroll
    for (int h = 0; h < 2; h++) {
        const int r = r0 + h * 8;
        const float* csr = nullptr;
        const float* snr = nullptr;
        if constexpr (EPI == 0) {
            int s = r & (SQ - 1);
            csr = cs + (size_t)s * DH; snr = sn + (size_t)s * DH;
        }
        if constexpr (EPI == 1) {
            int t = r % SK;
            if (t < 2240) {
                int p = t % 320;
                if (p >= 64) { csr = cs + (size_t)(p - 64) * DH; snr = sn + (size_t)(p - 64) * DH; }
            }
        }
#pragma unroll
        for (int nf = 0; nf < 32; nf++) {
            const int n = nf * 8 + nb;
            float x0 = acc[nf][h * 2 + 0] + bias[n];
            float x1 = acc[nf][h * 2 + 1] + bias[n + 1];
            if constexpr (EPI == 0) {
                float cv = csr[n], sv = snr[n];
                float y0 = (x0 * cv - x1 * sv) * QSCALE;
                float y1 = (x1 * cv + x0 * sv) * QSCALE;
                *(__half2*)&g_Q[(size_t)r * DH + n] = __floats2half2_rn(y0, y1);
            } else if constexpr (EPI == 1) {
                float y0 = x0, y1 = x1;
                if (csr) {
                    float cv = csr[n], sv = snr[n];
                    y0 = x0 * cv - x1 * sv;
                    y1 = x1 * cv + x0 * sv;
                }
                *(__half2*)&g_K[(size_t)r * DH + n] = __floats2half2_rn(y0, y1);
            } else {
                *(__half2*)&g_V[(size_t)r * DH + n] = __floats2half2_rn(x0, x1);
            }
        }
    }
}

// merged q/k/v projection: blocks [0,256)=Q, [256,400)=K, [400,544)=V
__global__ __launch_bounds__(256, 1)
void qkv_kernel(const float* __restrict__ q_b, const float* __restrict__ k_b,
                const float* __restrict__ v_b,
                const float* __restrict__ cosq, const float* __restrict__ sinq,
                const float* __restrict__ cosk, const float* __restrict__ sink)
{
    extern __shared__ __half sm[];
    const int bx = blockIdx.x;
    if (bx < 256)      proj_body<256, 0>(bx * 128, g_Aq, g_Wq, q_b, cosq, sinq, sm);
    else if (bx < 400) proj_body<64, 1>((bx - 256) * 128, g_Ak, g_Wk, k_b, cosk, sink, sm);
    else               proj_body<64, 2>((bx - 400) * 128, g_Av, g_Wv, v_b, nullptr, nullptr, sm);
}

// ---------------------------------------------------------------------------
// Flash attention + fused output projection.
// Mainloop (R8/R10 form): prefetch K[i+1],V[i] -> softmax(i-1) -> QK(i) ->
// PV(i-1). Epilogue: Wo staged into dead K/V smem; O repacked C->A frags in
// registers; 16x256x256 GEMM per warp writes fp32 out + bias.
// smem: Q[128*264] | K[2*64*264] | V[2*64*264] halfs = 202752 bytes.
// Wo tile (256 rows x 264 pitch) occupies K region + V region exactly.
// ---------------------------------------------------------------------------
constexpr int BM = 128, BN = 64, DP = 264;   // 528B pitch == 16 mod 128
constexpr int NCH = SK / BN;                 // 36
constexpr int SMEM_FLASH = (BM * DP + 4 * BN * DP) * 2;   // 202752

__global__ __launch_bounds__(256, 1)
void flash_kernel(const float* __restrict__ o_b, float* __restrict__ out)
{
    extern __shared__ __half sm[];
    const int tid = threadIdx.x;
    const int b   = blockIdx.y;
    const int m0  = blockIdx.x * BM;

    const __half* Qgp = g_Q + ((size_t)b * SQ + m0) * DH;
    const __half* Kgp = g_K + (size_t)b * SK * DH;
    const __half* Vgp = g_V + (size_t)b * SK * DH;

    const uint32_t QsB = cvta_s(sm);
    const uint32_t KsB = QsB + BM * DP * 2;
    const uint32_t VsB = KsB + 2 * BN * DP * 2;

    // prologue: Q + K0, then K1 + V0
    for (int i = tid; i < BM * 32; i += 256) {
        int r = i >> 5, c = i & 31;
        cpa16(QsB + (uint32_t)((r * DP + c * 8) * 2), Qgp + (size_t)r * DH + c * 8);
    }
    for (int i = tid; i < BN * 32; i += 256) {
        int r = i >> 5, c = i & 31;
        cpa16(KsB + (uint32_t)((r * DP + c * 8) * 2), Kgp + (size_t)r * DH + c * 8);
    }
    cpa_commit();
    for (int i = tid; i < BN * 32; i += 256) {
        int r = i >> 5, c = i & 31;
        cpa16(KsB + (uint32_t)(BN * DP * 2 + (r * DP + c * 8) * 2),
              Kgp + (size_t)(BN + r) * DH + c * 8);
        cpa16(VsB + (uint32_t)((r * DP + c * 8) * 2), Vgp + (size_t)r * DH + c * 8);
    }
    cpa_commit();
    cpa_wait0();
    __syncthreads();

    const int warp = tid >> 5, lane = tid & 31;
    const int mb   = warp * 16;

    float oacc[32][4];
#pragma unroll
    for (int i = 0; i < 32; i++) { oacc[i][0] = oacc[i][1] = oacc[i][2] = oacc[i][3] = 0.f; }
    float l0 = 0.f, l1 = 0.f;
    float sacc[8][4];
    uint32_t pfr[8][2];

    const uint32_t aQBase =
        QsB + (uint32_t)((((mb + (lane & 15)) * DP) + (lane >> 4) * 8) * 2);
    const int bmi = lane >> 3, bri = lane & 7;

    auto do_qk = [&](uint32_t Kc) {
#pragma unroll
        for (int i = 0; i < 8; i++) { sacc[i][0] = sacc[i][1] = sacc[i][2] = sacc[i][3] = 0.f; }
#pragma unroll
        for (int kk = 0; kk < DH; kk += 16) {
            uint32_t a[4];
            ldsm_x4(a, aQBase + kk * 2);
#pragma unroll
            for (int jn = 0; jn < 8; jn += 2) {
                uint32_t bf[4];
                int rowB = jn * 8 + (bmi >> 1) * 8 + bri;
                int colB = kk + (bmi & 1) * 8;
                ldsm_x4(bf, Kc + (uint32_t)((rowB * DP + colB) * 2));
                mma16816(sacc[jn],     a, bf[0], bf[1]);
                mma16816(sacc[jn + 1], a, bf[2], bf[3]);
            }
        }
    };
    auto do_pv = [&](uint32_t Vc) {
#pragma unroll
        for (int ks = 0; ks < 4; ks++) {
            uint32_t a2[4] = { pfr[2 * ks][0], pfr[2 * ks][1],
                               pfr[2 * ks + 1][0], pfr[2 * ks + 1][1] };
#pragma unroll
            for (int nf = 0; nf < 32; nf += 2) {
                uint32_t bf[4];
                int rowV = ks * 16 + (bmi & 1) * 8 + bri;
                int colV = nf * 8 + (bmi >> 1) * 8;
                ldsm_x4_t(bf, Vc + (uint32_t)((rowV * DP + colV) * 2));
                mma16816(oacc[nf],     a2, bf[0], bf[1]);
                mma16816(oacc[nf + 1], a2, bf[2], bf[3]);
            }
        }
    };

    do_qk(KsB);          // S(0)
    __syncthreads();     // K buf 0 fully read before iter-1 prefetch

    const __half2 clamp15 = __float2half2_rn(15.f);

#pragma unroll 1
    for (int i = 1; i <= NCH; i++) {
        if (i < NCH) {
            if (i + 1 < NCH) {   // K[i+1] -> buf (i+1)&1
                const __half* Kn = Kgp + (size_t)(i + 1) * BN * DH;
                const uint32_t Kd = KsB + (uint32_t)(((i + 1) & 1) * BN * DP * 2);
                for (int t = tid; t < BN * 32; t += 256) {
                    int r = t >> 5, c = t & 31;
                    cpa16(Kd + (uint32_t)((r * DP + c * 8) * 2), Kn + (size_t)r * DH + c * 8);
                }
            }
            {                    // V[i] -> buf i&1
                const __half* Vn = Vgp + (size_t)i * BN * DH;
                const uint32_t Vd = VsB + (uint32_t)((i & 1) * BN * DP * 2);
                for (int t = tid; t < BN * 32; t += 256) {
                    int r = t >> 5, c = t & 31;
                    cpa16(Vd + (uint32_t)((r * DP + c * 8) * 2), Vn + (size_t)r * DH + c * 8);
                }
            }
            cpa_commit();
        } else {
            // last iteration: K region + V buf0 are dead -> stage Wo rows 0..191
            for (int t = tid; t < 192 * 32; t += 256) {
                int n = t >> 5, c = t & 31;
                cpa16(KsB + (uint32_t)((n * DP + c * 8) * 2), g_Wo + (size_t)n * DH + c * 8);
            }
            cpa_commit();
        }

        // softmax(i-1): old sacc -> pfr, l  (f16x2; hides under QK(i))
        __half2 t0 = __float2half2_rn(0.f), t1 = __float2half2_rn(0.f);
#pragma unroll
        for (int j = 0; j < 8; j++) {
            __half2 h0 = __floats2half2_rn(sacc[j][0], sacc[j][1]);
            __half2 h1 = __floats2half2_rn(sacc[j][2], sacc[j][3]);
            h0 = h2exp2(__hmin2(h0, clamp15));
            h1 = h2exp2(__hmin2(h1, clamp15));
            pfr[j][0] = *(uint32_t*)&h0;
            pfr[j][1] = *(uint32_t*)&h1;
            t0 = __hadd2(t0, h0);
            t1 = __hadd2(t1, h1);
        }
        {
            float2 f0 = __half22float2(t0), f1 = __half22float2(t1);
            l0 += f0.x + f0.y;
            l1 += f1.x + f1.y;
        }

        if (i < NCH) do_qk(KsB + (uint32_t)((i & 1) * BN * DP * 2));   // S(i)
        do_pv(VsB + (uint32_t)(((i - 1) & 1) * BN * DP * 2));          // O += P(i-1)@V

        if (i < NCH) { cpa_wait0(); __syncthreads(); }
    }

    // ---- fused output projection ----
    __syncthreads();   // all warps done reading V buf1 (final PV)
    // stage Wo rows 192..255 into the V buf1 area (contiguous with K region)
    for (int t = tid; t < 64 * 32; t += 256) {
        int n = 192 + (t >> 5), c = t & 31;
        cpa16(KsB + (uint32_t)((n * DP + c * 8) * 2), g_Wo + (size_t)n * DH + c * 8);
    }
    cpa_commit();

    // row sums -> 1/l
    l0 += __shfl_xor_sync(0xffffffffu, l0, 1);
    l0 += __shfl_xor_sync(0xffffffffu, l0, 2);
    l1 += __shfl_xor_sync(0xffffffffu, l1, 1);
    l1 += __shfl_xor_sync(0xffffffffu, l1, 2);
    const float inv0 = 1.f / l0, inv1 = 1.f / l1;

    // pack normalized O (C-fragments) into fp16 A-fragments (same ordering
    // as the pfr operand packing used in do_pv)
    uint32_t af[16][4];
#pragma unroll
    for (int j = 0; j < 16; j++) {
        __half2 p0 = __floats2half2_rn(oacc[2 * j][0] * inv0,     oacc[2 * j][1] * inv0);
        __half2 p1 = __floats2half2_rn(oacc[2 * j][2] * inv1,     oacc[2 * j][3] * inv1);
        __half2 p2 = __floats2half2_rn(oacc[2 * j + 1][0] * inv0, oacc[2 * j + 1][1] * inv0);
        __half2 p3 = __floats2half2_rn(oacc[2 * j + 1][2] * inv1, oacc[2 * j + 1][3] * inv1);
        af[j][0] = *(uint32_t*)&p0;
        af[j][1] = *(uint32_t*)&p1;
        af[j][2] = *(uint32_t*)&p2;
        af[j][3] = *(uint32_t*)&p3;
    }

    cpa_wait0();
    __syncthreads();   // Wo fully staged, visible to all warps

    // out[16 rows x 256 cols] = Onorm @ Wo^T + o_b, in two 128-col halves
    const size_t rowbase = (size_t)b * SQ + m0 + mb + (lane >> 2);
#pragma unroll
    for (int hb = 0; hb < 2; hb++) {
        float acc2[16][4];
#pragma unroll
        for (int i = 0; i < 16; i++) { acc2[i][0] = acc2[i][1] = acc2[i][2] = acc2[i][3] = 0.f; }
#pragma unroll
        for (int j = 0; j < 16; j++) {
#pragma unroll
            for (int nf = 0; nf < 16; nf += 2) {
                uint32_t bf[4];
                int rowB = hb * 128 + nf * 8 + (bmi >> 1) * 8 + bri;
                int colB = j * 16 + (bmi & 1) * 8;
                ldsm_x4(bf, KsB + (uint32_t)((rowB * DP + colB) * 2));
                mma16816(acc2[nf],     af[j], bf[0], bf[1]);
                mma16816(acc2[nf + 1], af[j], bf[2], bf[3]);
            }
        }
#pragma unroll
        for (int nf = 0; nf < 16; nf++) {
            const int n = hb * 128 + nf * 8 + (lane & 3) * 2;
            const float2 bb = *(const float2*)&o_b[n];
            *(float2*)&out[rowbase * DH + n] =
                make_float2(acc2[nf][0] + bb.x, acc2[nf][1] + bb.y);
            *(float2*)&out[(rowbase + 8) * DH + n] =
                make_float2(acc2[nf][2] + bb.x, acc2[nf][3] + bb.y);
        }
    }
}

// ---------------------------------------------------------------------------
extern "C" void kernel_launch(void* const* d_in, const int* in_sizes, int n_in,
                              void* d_out, int out_size)
{
    (void)in_sizes; (void)n_in; (void)out_size;
    const float* query = (const float*)d_in[0];
    const float* key   = (const float*)d_in[1];
    const float* value = (const float*)d_in[2];
    const float* q_w   = (const float*)d_in[3];
    const float* q_b   = (const float*)d_in[4];
    const float* k_w   = (const float*)d_in[5];
    const float* k_b   = (const float*)d_in[6];
    const float* v_w   = (const float*)d_in[7];
    const float* v_b   = (const float*)d_in[8];
    const float* o_w   = (const float*)d_in[9];
    const float* o_b   = (const float*)d_in[10];
    const float* cosq  = (const float*)d_in[11];
    const float* sinq  = (const float*)d_in[12];
    const float* cosk  = (const float*)d_in[13];
    const float* sink  = (const float*)d_in[14];
    float* out = (float*)d_out;

    constexpr int SMEM_BIG = (256 + 128) * 264 * 2;  // 202752

    cudaFuncSetAttribute(qkv_kernel,   cudaFuncAttributeMaxDynamicSharedMemorySize, SMEM_BIG);
    cudaFuncSetAttribute(flash_kernel, cudaFuncAttributeMaxDynamicSharedMemorySize, SMEM_FLASH);

    cvt_kernel<<<CVT_BLOCKS, 256>>>(query, key, value, q_w, k_w, v_w, o_w);
    qkv_kernel<<<544, 256, SMEM_BIG>>>(q_b, k_b, v_b, cosq, sinq, cosk, sink);
    flash_kernel<<<dim3(SQ / BM, BB), 256, SMEM_FLASH>>>(o_b, out);
}

// round 14
// speedup vs baseline: 1.0652x; 1.0049x over previous
#include <cuda_runtime.h>
#include <cuda_fp16.h>
#include <cstdint>
#include <cstdio>

// ---------------------------------------------------------------------------
// EdgeTAM RoPE cross-attention, sm_100a (compute_100 target: no tcgen05).
// R14: R13 + q-projection FUSED into flash's prologue:
//   - Wq staged into the (empty) K/V smem regions, query tile into Q region
//   - 128x256x256 GEMM + bias + RoPE + scale, fp16 Q written IN PLACE
//   - g_Q eliminated; qkv kernel shrinks to K/V only (288 blocks)
//   Flash retains R13's fused o-projection epilogue.
// ---------------------------------------------------------------------------

#define DEVFN __device__ __forceinline__

constexpr int BB   = 8;
constexpr int SQ   = 4096;
constexpr int SK   = 2304;
constexpr int DH   = 256;
constexpr int MQ   = BB * SQ;   // 32768
constexpr int MK   = BB * SK;   // 18432
constexpr float QSCALE = 0.0625f * 1.4426950408889634f;  // 1/16 * log2(e)

// fp16 scratch
__device__ __align__(16) __half g_K[(size_t)MK * DH];
__device__ __align__(16) __half g_V[(size_t)MK * DH];
// fp16 copies of inputs / weights (pre-converted)
__device__ __align__(16) __half g_Aq[(size_t)MQ * DH];
__device__ __align__(16) __half g_Ak[(size_t)MK * 64];
__device__ __align__(16) __half g_Av[(size_t)MK * 64];
__device__ __align__(16) __half g_Wq[256 * 256];
__device__ __align__(16) __half g_Wk[256 * 64];
__device__ __align__(16) __half g_Wv[256 * 64];
__device__ __align__(16) __half g_Wo[256 * 256];

DEVFN uint32_t cvta_s(const void* p) { return (uint32_t)__cvta_generic_to_shared(p); }

DEVFN void ldsm_x4(uint32_t* r, uint32_t addr) {
    asm volatile("ldmatrix.sync.aligned.m8n8.x4.shared.b16 {%0,%1,%2,%3},[%4];"
                 : "=r"(r[0]), "=r"(r[1]), "=r"(r[2]), "=r"(r[3]) : "r"(addr));
}
DEVFN void ldsm_x4_t(uint32_t* r, uint32_t addr) {
    asm volatile("ldmatrix.sync.aligned.m8n8.x4.trans.shared.b16 {%0,%1,%2,%3},[%4];"
                 : "=r"(r[0]), "=r"(r[1]), "=r"(r[2]), "=r"(r[3]) : "r"(addr));
}
DEVFN void mma16816(float* c, const uint32_t* a, uint32_t b0, uint32_t b1) {
    asm volatile("mma.sync.aligned.m16n8k16.row.col.f32.f16.f16.f32 "
                 "{%0,%1,%2,%3},{%4,%5,%6,%7},{%8,%9},{%0,%1,%2,%3};"
                 : "+f"(c[0]), "+f"(c[1]), "+f"(c[2]), "+f"(c[3])
                 : "r"(a[0]), "r"(a[1]), "r"(a[2]), "r"(a[3]), "r"(b0), "r"(b1));
}
DEVFN void cpa16(uint32_t dst, const void* src) {
    asm volatile("cp.async.cg.shared.global [%0],[%1],16;" :: "r"(dst), "l"(src));
}
DEVFN void cpa_commit() { asm volatile("cp.async.commit_group;"); }
DEVFN void cpa_wait0()  { asm volatile("cp.async.wait_group 0;"); }
DEVFN void sts32(uint32_t addr, uint32_t v) {
    asm volatile("st.shared.b32 [%0], %1;" :: "r"(addr), "r"(v));
}

// ---------------------------------------------------------------------------
// Pre-convert: fp32 -> fp16 for inputs and weights (bandwidth-bound).
// ---------------------------------------------------------------------------
DEVFN void cvt8(const float* __restrict__ s, __half* __restrict__ d) {
    const float4 f0 = *(const float4*)s;
    const float4 f1 = *(const float4*)(s + 4);
    __half2 h[4] = { __floats2half2_rn(f0.x, f0.y), __floats2half2_rn(f0.z, f0.w),
                     __floats2half2_rn(f1.x, f1.y), __floats2half2_rn(f1.z, f1.w) };
    *(uint4*)d = *(uint4*)h;
}

constexpr size_t NQE  = (size_t)MQ * DH;
constexpr size_t NKE  = (size_t)MK * 64;
constexpr size_t NWQO = 256 * 256;
constexpr size_t NWKV = 256 * 64;
constexpr size_t NCVT = NQE + 2 * NKE + 2 * NWQO + 2 * NWKV;
constexpr int    CVT_BLOCKS = (int)(NCVT / 8 / 256);

__global__ __launch_bounds__(256, 8)
void cvt_kernel(const float* __restrict__ q, const float* __restrict__ k,
                const float* __restrict__ v,
                const float* __restrict__ wq, const float* __restrict__ wk,
                const float* __restrict__ wv, const float* __restrict__ wo)
{
    size_t i = ((size_t)blockIdx.x * 256 + threadIdx.x) * 8;
    if (i < NQE)  { cvt8(q  + i, g_Aq + i); return; }  i -= NQE;
    if (i < NKE)  { cvt8(k  + i, g_Ak + i); return; }  i -= NKE;
    if (i < NKE)  { cvt8(v  + i, g_Av + i); return; }  i -= NKE;
    if (i < NWQO) { cvt8(wq + i, g_Wq + i); return; }  i -= NWQO;
    if (i < NWKV) { cvt8(wk + i, g_Wk + i); return; }  i -= NWKV;
    if (i < NWKV) { cvt8(wv + i, g_Wv + i); return; }  i -= NWKV;
    cvt8(wo + i, g_Wo + i);
}

// ---------------------------------------------------------------------------
// K/V projection (KIN=64): 128x256 tile, cp.async fp16 fills.
// EPI: 1=k(rope_k->g_K) 2=v(->g_V)
// ---------------------------------------------------------------------------
template <int EPI>
__device__ void proj_body_kv(int m0, const __half* __restrict__ Ah,
                             const __half* __restrict__ Wh,
                             const float* __restrict__ bias,
                             const float* __restrict__ cs, const float* __restrict__ sn,
                             __half* smbase)
{
    constexpr int KIN = 64;
    constexpr int KP  = KIN + 8;
    constexpr int KC  = KIN / 8;
    __half* Ws = smbase;
    __half* As = smbase + 256 * KP;
    const int tid = threadIdx.x;
    const uint32_t WsB = cvta_s(Ws), AsB = cvta_s(As);

    for (int c = tid; c < 256 * KC; c += 256) {
        int n = c >> 3, k = (c & (KC - 1)) * 8;
        cpa16(WsB + (uint32_t)((n * KP + k) * 2), Wh + (size_t)n * KIN + k);
    }
    for (int c = tid; c < 128 * KC; c += 256) {
        int r = c >> 3, k = (c & (KC - 1)) * 8;
        cpa16(AsB + (uint32_t)((r * KP + k) * 2), Ah + (size_t)(m0 + r) * KIN + k);
    }
    cpa_commit(); cpa_wait0();
    __syncthreads();

    const int warp = tid >> 5, lane = tid & 31;
    const int mb   = warp * 16;

    float acc[32][4];
#pragma unroll
    for (int i = 0; i < 32; i++) { acc[i][0] = acc[i][1] = acc[i][2] = acc[i][3] = 0.f; }

    const uint32_t aBase =
        AsB + (uint32_t)((((mb + (lane & 15)) * KP) + (lane >> 4) * 8) * 2);
    const int bmi = lane >> 3, bri = lane & 7;

#pragma unroll
    for (int kk = 0; kk < KIN; kk += 16) {
        uint32_t a[4];
        ldsm_x4(a, aBase + kk * 2);
#pragma unroll
        for (int nf = 0; nf < 32; nf += 2) {
            uint32_t b[4];
            int rowB = nf * 8 + (bmi >> 1) * 8 + bri;
            int colB = kk + (bmi & 1) * 8;
            ldsm_x4(b, WsB + (uint32_t)((rowB * KP + colB) * 2));
            mma16816(acc[nf],     a, b[0], b[1]);
            mma16816(acc[nf + 1], a, b[2], b[3]);
        }
    }

    const int r0 = m0 + mb + (lane >> 2);
    const int nb = (lane & 3) * 2;
#pragma unroll
    for (int h = 0; h < 2; h++) {
        const int r = r0 + h * 8;
        const float* csr = nullptr;
        const float* snr = nullptr;
        if constexpr (EPI == 1) {
            int t = r % SK;
            if (t < 2240) {
                int p = t % 320;
                if (p >= 64) { csr = cs + (size_t)(p - 64) * DH; snr = sn + (size_t)(p - 64) * DH; }
            }
        }
#pragma unroll
        for (int nf = 0; nf < 32; nf++) {
            const int n = nf * 8 + nb;
            float x0 = acc[nf][h * 2 + 0] + bias[n];
            float x1 = acc[nf][h * 2 + 1] + bias[n + 1];
            if constexpr (EPI == 1) {
                float y0 = x0, y1 = x1;
                if (csr) {
                    float cv = csr[n], sv = snr[n];
                    y0 = x0 * cv - x1 * sv;
                    y1 = x1 * cv + x0 * sv;
                }
                *(__half2*)&g_K[(size_t)r * DH + n] = __floats2half2_rn(y0, y1);
            } else {
                *(__half2*)&g_V[(size_t)r * DH + n] = __floats2half2_rn(x0, x1);
            }
        }
    }
}

// k/v projection: blocks [0,144)=K, [144,288)=V
__global__ __launch_bounds__(256, 1)
void kv_kernel(const float* __restrict__ k_b, const float* __restrict__ v_b,
               const float* __restrict__ cosk, const float* __restrict__ sink)
{
    extern __shared__ __half sm[];
    const int bx = blockIdx.x;
    if (bx < 144) proj_body_kv<1>(bx * 128, g_Ak, g_Wk, k_b, cosk, sink, sm);
    else          proj_body_kv<2>((bx - 144) * 128, g_Av, g_Wv, v_b, nullptr, nullptr, sm);
}

// ---------------------------------------------------------------------------
// Flash attention + fused q-projection (prologue) + fused o-projection (epi).
// smem: Q[128*264] | K[2*64*264] | V[2*64*264] halfs = 202752 bytes.
// K+V regions = 256 contiguous rows of pitch DP -> stage Wq (prologue) and
// Wo (epilogue) there.
// ---------------------------------------------------------------------------
constexpr int BM = 128, BN = 64, DP = 264;   // 528B pitch == 16 mod 128
constexpr int NCH = SK / BN;                 // 36
constexpr int SMEM_FLASH = (BM * DP + 4 * BN * DP) * 2;   // 202752

__global__ __launch_bounds__(256, 1)
void flash_kernel(const float* __restrict__ q_b, const float* __restrict__ o_b,
                  const float* __restrict__ cosq, const float* __restrict__ sinq,
                  float* __restrict__ out)
{
    extern __shared__ __half sm[];
    const int tid = threadIdx.x;
    const int b   = blockIdx.y;
    const int m0  = blockIdx.x * BM;

    const __half* Kgp = g_K + (size_t)b * SK * DH;
    const __half* Vgp = g_V + (size_t)b * SK * DH;

    const uint32_t QsB = cvta_s(sm);
    const uint32_t KsB = QsB + BM * DP * 2;
    const uint32_t VsB = KsB + 2 * BN * DP * 2;

    const int warp = tid >> 5, lane = tid & 31;
    const int mb   = warp * 16;
    const int bmi  = lane >> 3, bri = lane & 7;

    // ===== fused q-projection prologue =====
    // stage query tile -> Q region, Wq -> K+V regions (256 contiguous rows)
    {
        const __half* Aqp = g_Aq + ((size_t)b * SQ + m0) * DH;
        for (int i = tid; i < BM * 32; i += 256) {
            int r = i >> 5, c = i & 31;
            cpa16(QsB + (uint32_t)((r * DP + c * 8) * 2), Aqp + (size_t)r * DH + c * 8);
        }
        for (int i = tid; i < 256 * 32; i += 256) {
            int n = i >> 5, c = i & 31;
            cpa16(KsB + (uint32_t)((n * DP + c * 8) * 2), g_Wq + (size_t)n * DH + c * 8);
        }
        cpa_commit(); cpa_wait0();
        __syncthreads();

        float acc[32][4];
#pragma unroll
        for (int i = 0; i < 32; i++) { acc[i][0] = acc[i][1] = acc[i][2] = acc[i][3] = 0.f; }
        const uint32_t aB =
            QsB + (uint32_t)((((mb + (lane & 15)) * DP) + (lane >> 4) * 8) * 2);
#pragma unroll
        for (int kk = 0; kk < DH; kk += 16) {
            uint32_t a[4];
            ldsm_x4(a, aB + kk * 2);
#pragma unroll
            for (int nf = 0; nf < 32; nf += 2) {
                uint32_t bf[4];
                int rowB = nf * 8 + (bmi >> 1) * 8 + bri;
                int colB = kk + (bmi & 1) * 8;
                ldsm_x4(bf, KsB + (uint32_t)((rowB * DP + colB) * 2));
                mma16816(acc[nf],     a, bf[0], bf[1]);
                mma16816(acc[nf + 1], a, bf[2], bf[3]);
            }
        }
        __syncthreads();   // all warps done reading the A tile before overwrite

        // bias + rope + scale -> fp16 Q written in place into the Q region
        const int rl0 = mb + (lane >> 2);
        const int nb  = (lane & 3) * 2;
#pragma unroll
        for (int h = 0; h < 2; h++) {
            const int rl = rl0 + h * 8;
            const int s  = (m0 + rl) & (SQ - 1);
            const float* csr = cosq + (size_t)s * DH;
            const float* snr = sinq + (size_t)s * DH;
#pragma unroll
            for (int nf = 0; nf < 32; nf++) {
                const int n = nf * 8 + nb;
                float x0 = acc[nf][h * 2 + 0] + q_b[n];
                float x1 = acc[nf][h * 2 + 1] + q_b[n + 1];
                float cv = csr[n], sv = snr[n];
                float y0 = (x0 * cv - x1 * sv) * QSCALE;
                float y1 = (x1 * cv + x0 * sv) * QSCALE;
                __half2 hv = __floats2half2_rn(y0, y1);
                sts32(QsB + (uint32_t)((rl * DP + n) * 2), *(uint32_t*)&hv);
            }
        }
        __syncthreads();   // Q tile ready for ldsm
    }

    // ===== load K0, K1, V0 (overwrites Wq) =====
    for (int i = tid; i < BN * 32; i += 256) {
        int r = i >> 5, c = i & 31;
        cpa16(KsB + (uint32_t)((r * DP + c * 8) * 2), Kgp + (size_t)r * DH + c * 8);
    }
    cpa_commit();
    for (int i = tid; i < BN * 32; i += 256) {
        int r = i >> 5, c = i & 31;
        cpa16(KsB + (uint32_t)(BN * DP * 2 + (r * DP + c * 8) * 2),
              Kgp + (size_t)(BN + r) * DH + c * 8);
        cpa16(VsB + (uint32_t)((r * DP + c * 8) * 2), Vgp + (size_t)r * DH + c * 8);
    }
    cpa_commit();
    cpa_wait0();
    __syncthreads();

    float oacc[32][4];
#pragma unroll
    for (int i = 0; i < 32; i++) { oacc[i][0] = oacc[i][1] = oacc[i][2] = oacc[i][3] = 0.f; }
    float l0 = 0.f, l1 = 0.f;
    float sacc[8][4];
    uint32_t pfr[8][2];

    const uint32_t aQBase =
        QsB + (uint32_t)((((mb + (lane & 15)) * DP) + (lane >> 4) * 8) * 2);

    auto do_qk = [&](uint32_t Kc) {
#pragma unroll
        for (int i = 0; i < 8; i++) { sacc[i][0] = sacc[i][1] = sacc[i][2] = sacc[i][3] = 0.f; }
#pragma unroll
        for (int kk = 0; kk < DH; kk += 16) {
            uint32_t a[4];
            ldsm_x4(a, aQBase + kk * 2);
#pragma unroll
            for (int jn = 0; jn < 8; jn += 2) {
                uint32_t bf[4];
                int rowB = jn * 8 + (bmi >> 1) * 8 + bri;
                int colB = kk + (bmi & 1) * 8;
                ldsm_x4(bf, Kc + (uint32_t)((rowB * DP + colB) * 2));
                mma16816(sacc[jn],     a, bf[0], bf[1]);
                mma16816(sacc[jn + 1], a, bf[2], bf[3]);
            }
        }
    };
    auto do_pv = [&](uint32_t Vc) {
#pragma unroll
        for (int ks = 0; ks < 4; ks++) {
            uint32_t a2[4] = { pfr[2 * ks][0], pfr[2 * ks][1],
                               pfr[2 * ks + 1][0], pfr[2 * ks + 1][1] };
#pragma unroll
            for (int nf = 0; nf < 32; nf += 2) {
                uint32_t bf[4];
                int rowV = ks * 16 + (bmi & 1) * 8 + bri;
                int colV = nf * 8 + (bmi >> 1) * 8;
                ldsm_x4_t(bf, Vc + (uint32_t)((rowV * DP + colV) * 2));
                mma16816(oacc[nf],     a2, bf[0], bf[1]);
                mma16816(oacc[nf + 1], a2, bf[2], bf[3]);
            }
        }
    };

    do_qk(KsB);          // S(0)
    __syncthreads();

    const __half2 clamp15 = __float2half2_rn(15.f);

#pragma unroll 1
    for (int i = 1; i <= NCH; i++) {
        if (i < NCH) {
            if (i + 1 < NCH) {
                const __half* Kn = Kgp + (size_t)(i + 1) * BN * DH;
                const uint32_t Kd = KsB + (uint32_t)(((i + 1) & 1) * BN * DP * 2);
                for (int t = tid; t < BN * 32; t += 256) {
                    int r = t >> 5, c = t & 31;
                    cpa16(Kd + (uint32_t)((r * DP + c * 8) * 2), Kn + (size_t)r * DH + c * 8);
                }
            }
            {
                const __half* Vn = Vgp + (size_t)i * BN * DH;
                const uint32_t Vd = VsB + (uint32_t)((i & 1) * BN * DP * 2);
                for (int t = tid; t < BN * 32; t += 256) {
                    int r = t >> 5, c = t & 31;
                    cpa16(Vd + (uint32_t)((r * DP + c * 8) * 2), Vn + (size_t)r * DH + c * 8);
                }
            }
            cpa_commit();
        } else {
            // last iteration: K region + V buf0 dead -> stage Wo rows 0..191
            for (int t = tid; t < 192 * 32; t += 256) {
                int n = t >> 5, c = t & 31;
                cpa16(KsB + (uint32_t)((n * DP + c * 8) * 2), g_Wo + (size_t)n * DH + c * 8);
            }
            cpa_commit();
        }

        __half2 t0 = __float2half2_rn(0.f), t1 = __float2half2_rn(0.f);
#pragma unroll
        for (int j = 0; j < 8; j++) {
            __half2 h0 = __floats2half2_rn(sacc[j][0], sacc[j][1]);
            __half2 h1 = __floats2half2_rn(sacc[j][2], sacc[j][3]);
            h0 = h2exp2(__hmin2(h0, clamp15));
            h1 = h2exp2(__hmin2(h1, clamp15));
            pfr[j][0] = *(uint32_t*)&h0;
            pfr[j][1] = *(uint32_t*)&h1;
            t0 = __hadd2(t0, h0);
            t1 = __hadd2(t1, h1);
        }
        {
            float2 f0 = __half22float2(t0), f1 = __half22float2(t1);
            l0 += f0.x + f0.y;
            l1 += f1.x + f1.y;
        }

        if (i < NCH) do_qk(KsB + (uint32_t)((i & 1) * BN * DP * 2));
        do_pv(VsB + (uint32_t)(((i - 1) & 1) * BN * DP * 2));

        if (i < NCH) { cpa_wait0(); __syncthreads(); }
    }

    // ===== fused output projection (R13) =====
    __syncthreads();   // final PV done reading V buf1
    for (int t = tid; t < 64 * 32; t += 256) {
        int n = 192 + (t >> 5), c = t & 31;
        cpa16(KsB + (uint32_t)((n * DP + c * 8) * 2), g_Wo + (size_t)n * DH + c * 8);
    }
    cpa_commit();

    l0 += __shfl_xor_sync(0xffffffffu, l0, 1);
    l0 += __shfl_xor_sync(0xffffffffu, l0, 2);
    l1 += __shfl_xor_sync(0xffffffffu, l1, 1);
    l1 += __shfl_xor_sync(0xffffffffu, l1, 2);
    const float inv0 = 1.f / l0, inv1 = 1.f / l1;

    uint32_t af[16][4];
#pragma unroll
    for (int j = 0; j < 16; j++) {
        __half2 p0 = __floats2half2_rn(oacc[2 * j][0] * inv0,     oacc[2 * j][1] * inv0);
        __half2 p1 = __floats2half2_rn(oacc[2 * j][2] * inv1,     oacc[2 * j][3] * inv1);
        __half2 p2 = __floats2half2_rn(oacc[2 * j + 1][0] * inv0, oacc[2 * j + 1][1] * inv0);
        __half2 p3 = __floats2half2_rn(oacc[2 * j + 1][2] * inv1, oacc[2 * j + 1][3] * inv1);
        af[j][0] = *(uint32_t*)&p0;
        af[j][1] = *(uint32_t*)&p1;
        af[j][2] = *(uint32_t*)&p2;
        af[j][3] = *(uint32_t*)&p3;
    }

    cpa_wait0();
    __syncthreads();

    const size_t rowbase = (size_t)b * SQ + m0 + mb + (lane >> 2);
#pragma unroll
    for (int hb = 0; hb < 2; hb++) {
        float acc2[16][4];
#pragma unroll
        for (int i = 0; i < 16; i++) { acc2[i][0] = acc2[i][1] = acc2[i][2] = acc2[i][3] = 0.f; }
#pragma unroll
        for (int j = 0; j < 16; j++) {
#pragma unroll
            for (int nf = 0; nf < 16; nf += 2) {
                uint32_t bf[4];
                int rowB = hb * 128 + nf * 8 + (bmi >> 1) * 8 + bri;
                int colB = j * 16 + (bmi & 1) * 8;
                ldsm_x4(bf, KsB + (uint32_t)((rowB * DP + colB) * 2));
                mma16816(acc2[nf],     af[j], bf[0], bf[1]);
                mma16816(acc2[nf + 1], af[j], bf[2], bf[3]);
            }
        }
#pragma unroll
        for (int nf = 0; nf < 16; nf++) {
            const int n = hb * 128 + nf * 8 + (lane & 3) * 2;
            const float2 bb = *(const float2*)&o_b[n];
            *(float2*)&out[rowbase * DH + n] =
                make_float2(acc2[nf][0] + bb.x, acc2[nf][1] + bb.y);
            *(float2*)&out[(rowbase + 8) * DH + n] =
                make_float2(acc2[nf][2] + bb.x, acc2[nf][3] + bb.y);
        }
    }
}

// ---------------------------------------------------------------------------
extern "C" void kernel_launch(void* const* d_in, const int* in_sizes, int n_in,
                              void* d_out, int out_size)
{
    (void)in_sizes; (void)n_in; (void)out_size;
    const float* query = (const float*)d_in[0];
    const float* key   = (const float*)d_in[1];
    const float* value = (const float*)d_in[2];
    const float* q_w   = (const float*)d_in[3];
    const float* q_b   = (const float*)d_in[4];
    const float* k_w   = (const float*)d_in[5];
    const float* k_b   = (const float*)d_in[6];
    const float* v_w   = (const float*)d_in[7];
    const float* v_b   = (const float*)d_in[8];
    const float* o_w   = (const float*)d_in[9];
    const float* o_b   = (const float*)d_in[10];
    const float* cosq  = (const float*)d_in[11];
    const float* sinq  = (const float*)d_in[12];
    const float* cosk  = (const float*)d_in[13];
    const float* sink  = (const float*)d_in[14];
    float* out = (float*)d_out;

    constexpr int SMEM_KV = (256 + 128) * 72 * 2;  // 55296

    cudaFuncSetAttribute(kv_kernel,    cudaFuncAttributeMaxDynamicSharedMemorySize, SMEM_KV);
    cudaFuncSetAttribute(flash_kernel, cudaFuncAttributeMaxDynamicSharedMemorySize, SMEM_FLASH);

    cvt_kernel<<<CVT_BLOCKS, 256>>>(query, key, value, q_w, k_w, v_w, o_w);
    kv_kernel<<<288, 256, SMEM_KV>>>(k_b, v_b, cosk, sink);
    flash_kernel<<<dim3(SQ / BM, BB), 256, SMEM_FLASH>>>(q_b, o_b, cosq, sinq, out);
}